// round 5
// baseline (speedup 1.0000x reference)
#include <cuda_runtime.h>
#include <cstdint>

// Packed fp32x2 FMA (Blackwell): 2x FFMA throughput, only reachable via PTX.
#define FMA2(d, a, b, c) \
    asm("fma.rn.f32x2 %0, %1, %2, %3;" : "=l"(d) : "l"(a), "l"(b), "l"(c))
#define MUL2(d, a, b) \
    asm("mul.rn.f32x2 %0, %1, %2;" : "=l"(d) : "l"(a), "l"(b))

__device__ __forceinline__ unsigned long long pack2(float lo, float hi) {
    unsigned long long r;
    asm("mov.b64 %0, {%1, %2};" : "=l"(r) : "f"(lo), "f"(hi));
    return r;
}
__device__ __forceinline__ void unpack2(unsigned long long p, float& lo, float& hi) {
    asm("mov.b64 {%0, %1}, %2;" : "=f"(lo), "=f"(hi) : "l"(p));
}
__device__ __forceinline__ float ex2f(float x) {
    float r;
    asm("ex2.approx.ftz.f32 %0, %1;" : "=f"(r) : "f"(x));
    return r;
}
// 16B shared load delivering two packed f32x2 (avoids pack MOVs).
__device__ __forceinline__ void lds_v2u64(unsigned long long& a, unsigned long long& b,
                                          uint32_t saddr) {
    asm volatile("ld.shared.v2.u64 {%0, %1}, [%2];" : "=l"(a), "=l"(b) : "r"(saddr));
}

static constexpr int D       = 64;
static constexpr int S       = 8192;
static constexpr int G       = 32;    // N_GLOBAL
static constexpr int OUTROWS = 7936;  // S - WINDOW/2
static constexpr int TQ      = 128;   // queries per CTA
static constexpr int TK      = 16;    // keys per smem tile
static constexpr int NTHREADS = 256;

__global__ __launch_bounds__(NTHREADS, 2)
void swa_kernel(const float* __restrict__ qg, const float* __restrict__ kg,
                const float* __restrict__ vg, float* __restrict__ outg)
{
    __shared__ float kbuf[TK * D];   // 4 KB
    __shared__ float vbuf[TK * D];   // 4 KB

    const int bh = blockIdx.y;
    const int qb = blockIdx.x;

    // Key range for this query block.
    int kstart, klen;
    if (qb < 2) { kstart = 0; klen = 256; }                 // first half-window block
    else { int c = (qb - 2) >> 2; kstart = 256 + 512 * c; klen = 512; }
    const int ntiles = 2 + klen / TK;   // 2 global tiles (rows 0..31) + local tiles

    const int tid  = threadIdx.x;
    const int w    = tid >> 5;
    const int lane = tid & 31;
    const int qrow = qb * TQ + w * 16 + (lane >> 1); // this thread's query row
    const int half = lane & 1;                        // which 32 dims of D=64

    // Fold 1/sqrt(D) * log2(e) into Q.
    const float SC = 0.125f * 1.44269504088896340736f;

    // Q in registers, packed f32x2: 16 x u64 = 32 floats.
    unsigned long long q2[16];
    {
        const float4* qp = (const float4*)(qg + ((size_t)bh * S + qrow) * D + half * 32);
        #pragma unroll
        for (int i = 0; i < 8; i++) {
            float4 t = qp[i];
            q2[2 * i]     = pack2(t.x * SC, t.y * SC);
            q2[2 * i + 1] = pack2(t.z * SC, t.w * SC);
        }
    }

    unsigned long long o2[16];
    #pragma unroll
    for (int i = 0; i < 16; i++) o2[i] = 0ull;
    float m = -1e30f, l = 0.f;

    const uint32_t ksm = (uint32_t)__cvta_generic_to_shared(kbuf);
    const uint32_t vsm = (uint32_t)__cvta_generic_to_shared(vbuf);
    const uint32_t hoff = (uint32_t)(half * 32 * 4);  // byte offset of this thread's half

    for (int t = 0; t < ntiles; t++) {
        const int krow = (t < 2) ? t * TK : kstart + (t - 2) * TK;

        // Cooperative tile load: 256 float4 per buffer, one per thread.
        {
            const int r = tid >> 4, c4 = tid & 15;
            const size_t gofs = ((size_t)bh * S + krow + r) * D + c4 * 4;
            ((float4*)kbuf)[tid] = *(const float4*)(kg + gofs);
            ((float4*)vbuf)[tid] = *(const float4*)(vg + gofs);
        }
        __syncthreads();

        // ---- scores: s[j] = (q . k_j) * scale * log2e ----
        float sarr[TK];
        #pragma unroll
        for (int j = 0; j < TK; j++) {
            unsigned long long acc = 0ull;
            const uint32_t base = ksm + (uint32_t)(j * D * 4) + hoff;
            #pragma unroll
            for (int i = 0; i < 8; i++) {
                unsigned long long k0, k1;
                lds_v2u64(k0, k1, base + i * 16);
                FMA2(acc, q2[2 * i],     k0, acc);
                FMA2(acc, q2[2 * i + 1], k1, acc);
            }
            float lo, hi;
            unpack2(acc, lo, hi);
            float s = lo + hi;
            s += __shfl_xor_sync(0xffffffffu, s, 1);  // combine the two halves
            sarr[j] = s;
        }

        // ---- online softmax (log2 domain) ----
        float tmax = sarr[0];
        #pragma unroll
        for (int j = 1; j < TK; j++) tmax = fmaxf(tmax, sarr[j]);
        const float mnew  = fmaxf(m, tmax);
        const float alpha = ex2f(m - mnew);
        m = mnew;
        l *= alpha;
        const unsigned long long a2 = pack2(alpha, alpha);
        #pragma unroll
        for (int i = 0; i < 16; i++) MUL2(o2[i], o2[i], a2);
        #pragma unroll
        for (int j = 0; j < TK; j++) {
            sarr[j] = ex2f(sarr[j] - mnew);   // reuse sarr as p[]
            l += sarr[j];
        }

        // ---- O += P V ----
        #pragma unroll
        for (int j = 0; j < TK; j++) {
            const unsigned long long p2 = pack2(sarr[j], sarr[j]);
            const uint32_t base = vsm + (uint32_t)(j * D * 4) + hoff;
            #pragma unroll
            for (int i = 0; i < 8; i++) {
                unsigned long long v0, v1;
                lds_v2u64(v0, v1, base + i * 16);
                FMA2(o2[2 * i],     p2, v0, o2[2 * i]);
                FMA2(o2[2 * i + 1], p2, v1, o2[2 * i + 1]);
            }
        }
        __syncthreads();
    }

    // ---- normalize + store ----
    const float inv = 1.f / l;
    const unsigned long long inv2 = pack2(inv, inv);
    float4* op = (float4*)(outg + ((size_t)bh * OUTROWS + qrow) * D + half * 32);
    #pragma unroll
    for (int i = 0; i < 8; i++) {
        unsigned long long r0, r1;
        MUL2(r0, o2[2 * i],     inv2);
        MUL2(r1, o2[2 * i + 1], inv2);
        float4 o4;
        unpack2(r0, o4.x, o4.y);
        unpack2(r1, o4.z, o4.w);
        op[i] = o4;
    }
}

extern "C" void kernel_launch(void* const* d_in, const int* in_sizes, int n_in,
                              void* d_out, int out_size)
{
    const float* q = (const float*)d_in[0];
    const float* k = (const float*)d_in[1];
    const float* v = (const float*)d_in[2];
    float* out = (float*)d_out;

    // 62 query-blocks of 128 rows per (b,h): 2 for the first 256 rows,
    // then 4 per 512-row chunk x 15 chunks. 32 = B*H.
    dim3 grid(62, 32);
    swa_kernel<<<grid, NTHREADS>>>(q, k, v, out);
}

// round 6
// speedup vs baseline: 6.8327x; 6.8327x over previous
#include <cuda_runtime.h>
#include <cstdint>

static constexpr int S_LEN   = 8192;
static constexpr int Dh      = 64;
static constexpr int OUTROWS = 7936;   // S - WINDOW/2
static constexpr int TK      = 32;     // keys per tile
static constexpr int PAD     = 68;     // smem row stride (f32) -> conflict-free frags
static constexpr int NT      = 128;    // threads per CTA (4 warps x 32 q-rows)

__device__ __forceinline__ uint32_t f2tf32(float x) {
    uint32_t r; asm("cvt.rna.tf32.f32 %0, %1;" : "=r"(r) : "f"(x)); return r;
}
__device__ __forceinline__ float ex2f(float x) {
    float r; asm("ex2.approx.ftz.f32 %0, %1;" : "=f"(r) : "f"(x)); return r;
}
// D += A * B, m16n8k8 tf32, in-place accumulate.
__device__ __forceinline__ void mma8(float d[4], const uint32_t a[4], const uint32_t b[2]) {
    asm("mma.sync.aligned.m16n8k8.row.col.f32.tf32.tf32.f32 "
        "{%0,%1,%2,%3}, {%4,%5,%6,%7}, {%8,%9}, {%0,%1,%2,%3};"
        : "+f"(d[0]), "+f"(d[1]), "+f"(d[2]), "+f"(d[3])
        : "r"(a[0]), "r"(a[1]), "r"(a[2]), "r"(a[3]), "r"(b[0]), "r"(b[1]));
}

__global__ __launch_bounds__(NT)
void swa_mma(const float* __restrict__ qg, const float* __restrict__ kg,
             const float* __restrict__ vg, float* __restrict__ outg)
{
    __shared__ float kbuf[2][TK * PAD];   // 8.5 KB each
    __shared__ float vbuf[2][TK * PAD];

    const int bh = blockIdx.y, qb = blockIdx.x;
    int kstart, klen;
    if (qb < 2) { kstart = 0; klen = 256; }
    else        { kstart = 256 + 512 * ((qb - 2) >> 2); klen = 512; }
    const int nt = 1 + klen / TK;   // tile 0 = 32 global keys, then local tiles

    const int tid  = threadIdx.x;
    const int warp = tid >> 5, lane = tid & 31;
    const int g = lane >> 2, tig = lane & 3;

    const float C = 0.125f * 1.44269504088896340736f;  // scale * log2(e)
    const size_t kvbase = (size_t)bh * S_LEN * Dh;

    // ---- Q fragments (RNA-rounded tf32), resident: [kb=8][rb=2][4 regs] ----
    uint32_t qf[8][2][4];
    {
        const float* qp = qg + kvbase + (size_t)(qb * 128 + warp * 32) * Dh;
        #pragma unroll
        for (int kb = 0; kb < 8; kb++)
            #pragma unroll
            for (int rb = 0; rb < 2; rb++) {
                const int r0 = rb * 16 + g;
                const int c0 = kb * 8 + tig;
                qf[kb][rb][0] = f2tf32(qp[(r0    ) * Dh + c0    ]);
                qf[kb][rb][1] = f2tf32(qp[(r0 + 8) * Dh + c0    ]);
                qf[kb][rb][2] = f2tf32(qp[(r0    ) * Dh + c0 + 4]);
                qf[kb][rb][3] = f2tf32(qp[(r0 + 8) * Dh + c0 + 4]);
            }
    }

    float o[2][8][4];
    #pragma unroll
    for (int rb = 0; rb < 2; rb++)
        #pragma unroll
        for (int nb = 0; nb < 8; nb++)
            #pragma unroll
            for (int i = 0; i < 4; i++) o[rb][nb][i] = 0.f;
    float mrow[2][2] = {{-1e30f, -1e30f}, {-1e30f, -1e30f}};
    float lrow[2][2] = {{0.f, 0.f}, {0.f, 0.f}};

    const float4* kp4 = (const float4*)(kg + kvbase);
    const float4* vp4 = (const float4*)(vg + kvbase);
    float4 stk[4], stv[4];

    // Prologue: stage tile 0 (rows 0..31 = global keys).
    {
        #pragma unroll
        for (int j = 0; j < 4; j++) { stk[j] = kp4[tid + NT * j]; stv[j] = vp4[tid + NT * j]; }
        #pragma unroll
        for (int j = 0; j < 4; j++) {
            const int f4i = tid + NT * j, row = f4i >> 4, c = f4i & 15;
            float4 a = stk[j];
            float4 rk = { __uint_as_float(f2tf32(a.x)), __uint_as_float(f2tf32(a.y)),
                          __uint_as_float(f2tf32(a.z)), __uint_as_float(f2tf32(a.w)) };
            *(float4*)&kbuf[0][row * PAD + c * 4] = rk;
            float4 b = stv[j];
            float4 rv = { __uint_as_float(f2tf32(b.x)), __uint_as_float(f2tf32(b.y)),
                          __uint_as_float(f2tf32(b.z)), __uint_as_float(f2tf32(b.w)) };
            *(float4*)&vbuf[0][row * PAD + c * 4] = rv;
        }
    }
    __syncthreads();

    for (int t = 0; t < nt; t++) {
        const bool pf = (t + 1) < nt;
        const int nbuf = (t + 1) & 1;
        const float* ks = kbuf[t & 1];
        const float* vs = vbuf[t & 1];

        // Prefetch next tile's K into registers (latency hidden by S-gemm).
        if (pf) {
            const size_t roff = (size_t)(kstart + t * TK) * Dh / 4;  // next tile rows
            #pragma unroll
            for (int j = 0; j < 4; j++) stk[j] = kp4[roff + tid + NT * j];
        }

        // ---- S = Q K^T  (raw, unscaled) ----
        float sf[2][4][4];
        #pragma unroll
        for (int rb = 0; rb < 2; rb++)
            #pragma unroll
            for (int nb = 0; nb < 4; nb++)
                #pragma unroll
                for (int i = 0; i < 4; i++) sf[rb][nb][i] = 0.f;
        #pragma unroll
        for (int kb = 0; kb < 8; kb++) {
            uint32_t b[4][2];
            #pragma unroll
            for (int nb = 0; nb < 4; nb++) {
                const int base = (nb * 8 + g) * PAD + kb * 8 + tig;
                b[nb][0] = __float_as_uint(ks[base]);
                b[nb][1] = __float_as_uint(ks[base + 4]);
            }
            #pragma unroll
            for (int nb = 0; nb < 4; nb++) {
                mma8(sf[0][nb], qf[kb][0], b[nb]);
                mma8(sf[1][nb], qf[kb][1], b[nb]);
            }
        }

        // ---- online softmax (scale folded into exponent) ----
        #pragma unroll
        for (int rb = 0; rb < 2; rb++) {
            float r0 = -1e30f, r1 = -1e30f;
            #pragma unroll
            for (int nb = 0; nb < 4; nb++) {
                r0 = fmaxf(r0, fmaxf(sf[rb][nb][0], sf[rb][nb][1]));
                r1 = fmaxf(r1, fmaxf(sf[rb][nb][2], sf[rb][nb][3]));
            }
            r0 = fmaxf(r0, __shfl_xor_sync(0xffffffffu, r0, 1));
            r0 = fmaxf(r0, __shfl_xor_sync(0xffffffffu, r0, 2));
            r1 = fmaxf(r1, __shfl_xor_sync(0xffffffffu, r1, 1));
            r1 = fmaxf(r1, __shfl_xor_sync(0xffffffffu, r1, 2));
            const float mn0 = fmaxf(mrow[rb][0], r0);
            const float mn1 = fmaxf(mrow[rb][1], r1);
            const float al0 = ex2f((mrow[rb][0] - mn0) * C);
            const float al1 = ex2f((mrow[rb][1] - mn1) * C);
            mrow[rb][0] = mn0; mrow[rb][1] = mn1;
            const float mb0 = mn0 * C, mb1 = mn1 * C;
            float s0 = 0.f, s1 = 0.f;
            #pragma unroll
            for (int nb = 0; nb < 4; nb++) {
                float p0 = ex2f(fmaf(sf[rb][nb][0], C, -mb0));
                float p1 = ex2f(fmaf(sf[rb][nb][1], C, -mb0));
                float p2 = ex2f(fmaf(sf[rb][nb][2], C, -mb1));
                float p3 = ex2f(fmaf(sf[rb][nb][3], C, -mb1));
                s0 += p0 + p1; s1 += p2 + p3;
                sf[rb][nb][0] = __uint_as_float(f2tf32(p0));
                sf[rb][nb][1] = __uint_as_float(f2tf32(p1));
                sf[rb][nb][2] = __uint_as_float(f2tf32(p2));
                sf[rb][nb][3] = __uint_as_float(f2tf32(p3));
            }
            s0 += __shfl_xor_sync(0xffffffffu, s0, 1);
            s0 += __shfl_xor_sync(0xffffffffu, s0, 2);
            s1 += __shfl_xor_sync(0xffffffffu, s1, 1);
            s1 += __shfl_xor_sync(0xffffffffu, s1, 2);
            lrow[rb][0] = lrow[rb][0] * al0 + s0;
            lrow[rb][1] = lrow[rb][1] * al1 + s1;
            #pragma unroll
            for (int nb = 0; nb < 8; nb++) {
                o[rb][nb][0] *= al0; o[rb][nb][1] *= al0;
                o[rb][nb][2] *= al1; o[rb][nb][3] *= al1;
            }
        }

        // Drain K prefetch into smem; prefetch next V.
        if (pf) {
            #pragma unroll
            for (int j = 0; j < 4; j++) {
                const int f4i = tid + NT * j, row = f4i >> 4, c = f4i & 15;
                float4 a = stk[j];
                float4 rk = { __uint_as_float(f2tf32(a.x)), __uint_as_float(f2tf32(a.y)),
                              __uint_as_float(f2tf32(a.z)), __uint_as_float(f2tf32(a.w)) };
                *(float4*)&kbuf[nbuf][row * PAD + c * 4] = rk;
            }
            const size_t roff = (size_t)(kstart + t * TK) * Dh / 4;
            #pragma unroll
            for (int j = 0; j < 4; j++) stv[j] = vp4[roff + tid + NT * j];
        }

        // ---- O += P V ---- (P frags from S frags via quad shuffle)
        const int src0 = (lane & ~3) | (tig >> 1);
        const int src2 = src0 + 2;
        const bool odd = (lane & 1);
        #pragma unroll
        for (int kb = 0; kb < 4; kb++) {
            uint32_t a[2][4];
            #pragma unroll
            for (int rb = 0; rb < 2; rb++) {
                const float e0 = sf[rb][kb][0], e1 = sf[rb][kb][1];
                const float e2 = sf[rb][kb][2], e3 = sf[rb][kb][3];
                float t00 = __shfl_sync(0xffffffffu, e0, src0);
                float t01 = __shfl_sync(0xffffffffu, e1, src0);
                float t20 = __shfl_sync(0xffffffffu, e2, src0);
                float t21 = __shfl_sync(0xffffffffu, e3, src0);
                float t40 = __shfl_sync(0xffffffffu, e0, src2);
                float t41 = __shfl_sync(0xffffffffu, e1, src2);
                float t60 = __shfl_sync(0xffffffffu, e2, src2);
                float t61 = __shfl_sync(0xffffffffu, e3, src2);
                a[rb][0] = __float_as_uint(odd ? t01 : t00);
                a[rb][1] = __float_as_uint(odd ? t21 : t20);
                a[rb][2] = __float_as_uint(odd ? t41 : t40);
                a[rb][3] = __float_as_uint(odd ? t61 : t60);
            }
            #pragma unroll
            for (int nb = 0; nb < 8; nb++) {
                uint32_t b[2];
                const int base = (kb * 8 + tig) * PAD + nb * 8 + g;
                b[0] = __float_as_uint(vs[base]);
                b[1] = __float_as_uint(vs[base + 4 * PAD]);
                mma8(o[0][nb], a[0], b);
                mma8(o[1][nb], a[1], b);
            }
        }

        // Drain V prefetch, flip buffers.
        if (pf) {
            #pragma unroll
            for (int j = 0; j < 4; j++) {
                const int f4i = tid + NT * j, row = f4i >> 4, c = f4i & 15;
                float4 b = stv[j];
                float4 rv = { __uint_as_float(f2tf32(b.x)), __uint_as_float(f2tf32(b.y)),
                              __uint_as_float(f2tf32(b.z)), __uint_as_float(f2tf32(b.w)) };
                *(float4*)&vbuf[nbuf][row * PAD + c * 4] = rv;
            }
            __syncthreads();
        }
    }

    // ---- normalize + store ----
    #pragma unroll
    for (int rb = 0; rb < 2; rb++) {
        const float inv0 = 1.f / lrow[rb][0];
        const float inv1 = 1.f / lrow[rb][1];
        const int row0 = qb * 128 + warp * 32 + rb * 16 + g;
        float* op0 = outg + ((size_t)bh * OUTROWS + row0) * Dh;
        float* op1 = op0 + 8 * Dh;
        #pragma unroll
        for (int nb = 0; nb < 8; nb++) {
            const int col = nb * 8 + 2 * tig;
            float2 v0 = { o[rb][nb][0] * inv0, o[rb][nb][1] * inv0 };
            *(float2*)(op0 + col) = v0;
            float2 v1 = { o[rb][nb][2] * inv1, o[rb][nb][3] * inv1 };
            *(float2*)(op1 + col) = v1;
        }
    }
}

extern "C" void kernel_launch(void* const* d_in, const int* in_sizes, int n_in,
                              void* d_out, int out_size)
{
    const float* q = (const float*)d_in[0];
    const float* k = (const float*)d_in[1];
    const float* v = (const float*)d_in[2];
    float* out = (float*)d_out;

    dim3 grid(62, 32);   // 62 q-blocks of 128 rows x 32 (b,h)
    swa_mma<<<grid, NT>>>(q, k, v, out);
}